// round 15
// baseline (speedup 1.0000x reference)
#include <cuda_runtime.h>
#include <cstdint>

#define LQ 2048
#define DIM 128
#define NB 8
#define KSPLIT 8
#define ROWS (NB*LQ)
#define NELE ((size_t)ROWS * DIM)
#define PAIR_ELE ((size_t)2 * LQ * DIM)

// deterministic scratch (no allocations allowed)
__device__ float g_rowsum_part[16][ROWS];            // 1 MB
__device__ float g_inv[ROWS];                        // 64 KB
__device__ float g_pout[KSPLIT][PAIR_ELE];           // 16 MB (pair-local, reused)

// ---------- helpers ----------
static __device__ __forceinline__ float tf32r(float x) {
    uint32_t u;
    asm("cvt.rna.tf32.f32 %0, %1;" : "=r"(u) : "f"(x));
    return __uint_as_float(u);
}

static __device__ __forceinline__ void mma8(float c[4], const float a[4], const float b[2]) {
    asm volatile(
        "mma.sync.aligned.m16n8k8.row.col.f32.tf32.tf32.f32 "
        "{%0,%1,%2,%3}, {%4,%5,%6,%7}, {%8,%9}, {%0,%1,%2,%3};\n"
        : "+f"(c[0]), "+f"(c[1]), "+f"(c[2]), "+f"(c[3])
        : "r"(__float_as_uint(a[0])), "r"(__float_as_uint(a[1])),
          "r"(__float_as_uint(a[2])), "r"(__float_as_uint(a[3])),
          "r"(__float_as_uint(b[0])), "r"(__float_as_uint(b[1])));
}

static __device__ __forceinline__ void cp16(void* dst, const void* src) {
    unsigned sd = (unsigned)__cvta_generic_to_shared(dst);
    asm volatile("cp.async.ca.shared.global [%0], [%1], 16;" :: "r"(sd), "l"(src));
}
static __device__ __forceinline__ void cp4(void* dst, const void* src) {
    unsigned sd = (unsigned)__cvta_generic_to_shared(dst);
    asm volatile("cp.async.ca.shared.global [%0], [%1], 4;" :: "r"(sd), "l"(src));
}
#define CPC  asm volatile("cp.async.commit_group;")
#define CPW1 asm volatile("cp.async.wait_group 1;")
#define CPW0 asm volatile("cp.async.wait_group 0;")

// ===== Kernel 1: p = tf32(exp((tf32(q) @ tf32(v)^T) * sc)) + rowsum partials =====
// 4 warps, 64x64 warp tiles. Processes batch pair [b2, b2+1]. (R14-proven internals)
__global__ __launch_bounds__(128, 2) void k_scores_exp(
    const float* __restrict__ q, const float* __restrict__ v,
    float* __restrict__ attn, int b2)
{
    __shared__ float Qs[2][128][20];
    __shared__ float Vs[2][128][20];
    __shared__ float rs[128][2];

    const int b  = b2 + blockIdx.z;
    const int jb = blockIdx.x;
    const int i0 = blockIdx.y * 128;
    const int j0 = jb * 128;

    const int tid  = threadIdx.x;
    const int lane = tid & 31;
    const int warp = tid >> 5;          // 0..3
    const int wm = (warp >> 1) * 64;
    const int wn = (warp & 1) * 64;
    const int g   = lane >> 2;
    const int kc4 = lane & 3;

    const float* qb = q + ((size_t)b * LQ + i0) * DIM;
    const float* vb = v + ((size_t)b * LQ + j0) * DIM;

    const int lr  = tid >> 2;           // 0..31
    const int lcc = (tid & 3) * 4;      // 0,4,8,12

    float acc[4][8][4];
    #pragma unroll
    for (int mt = 0; mt < 4; mt++)
        #pragma unroll
        for (int nt = 0; nt < 8; nt++)
            #pragma unroll
            for (int e = 0; e < 4; e++) acc[mt][nt][e] = 0.0f;

    #pragma unroll
    for (int h = 0; h < 4; h++) {
        cp16(&Qs[0][lr + h * 32][lcc], qb + (size_t)(lr + h * 32) * DIM + lcc);
        cp16(&Vs[0][lr + h * 32][lcc], vb + (size_t)(lr + h * 32) * DIM + lcc);
    }
    CPC;

    #pragma unroll
    for (int kt = 0; kt < 8; kt++) {
        const int st = kt & 1;
        if (kt < 7) {
            const int k0 = (kt + 1) * 16;
            const int sn = st ^ 1;
            #pragma unroll
            for (int h = 0; h < 4; h++) {
                cp16(&Qs[sn][lr + h * 32][lcc], qb + (size_t)(lr + h * 32) * DIM + k0 + lcc);
                cp16(&Vs[sn][lr + h * 32][lcc], vb + (size_t)(lr + h * 32) * DIM + k0 + lcc);
            }
            CPC; CPW1;
        } else {
            CPW0;
        }
        __syncthreads();

        #pragma unroll
        for (int kk = 0; kk < 16; kk += 8) {
            const int kc = kk + kc4;
            float af[4][4], bf[8][2];
            #pragma unroll
            for (int mt = 0; mt < 4; mt++) {
                const int r = wm + mt * 16 + g;
                af[mt][0] = tf32r(Qs[st][r][kc]);
                af[mt][1] = tf32r(Qs[st][r + 8][kc]);
                af[mt][2] = tf32r(Qs[st][r][kc + 4]);
                af[mt][3] = tf32r(Qs[st][r + 8][kc + 4]);
            }
            #pragma unroll
            for (int nt = 0; nt < 8; nt++) {
                const int n = wn + nt * 8 + g;
                bf[nt][0] = tf32r(Vs[st][n][kc]);
                bf[nt][1] = tf32r(Vs[st][n][kc + 4]);
            }
            #pragma unroll
            for (int mt = 0; mt < 4; mt++)
                #pragma unroll
                for (int nt = 0; nt < 8; nt++)
                    mma8(acc[mt][nt], af[mt], bf[nt]);
        }
        __syncthreads();
    }

    // epilogue: scale, exp, tf32-round, store, rowsum partials
    const float sc = 0.08838834764831845f;   // 1/sqrt(128)
    float* op = attn + ((size_t)b * LQ + i0) * LQ + j0;
    #pragma unroll
    for (int mt = 0; mt < 4; mt++) {
        const int r0 = wm + mt * 16 + g;
        float s0 = 0.0f, s1 = 0.0f;
        #pragma unroll
        for (int nt = 0; nt < 8; nt++) {
            const int c0 = wn + nt * 8 + kc4 * 2;
            float p0 = tf32r(__expf(acc[mt][nt][0] * sc));
            float p1 = tf32r(__expf(acc[mt][nt][1] * sc));
            float p2 = tf32r(__expf(acc[mt][nt][2] * sc));
            float p3 = tf32r(__expf(acc[mt][nt][3] * sc));
            *(float2*)(op + (size_t)r0 * LQ + c0)       = make_float2(p0, p1);
            *(float2*)(op + (size_t)(r0 + 8) * LQ + c0) = make_float2(p2, p3);
            s0 += p0 + p1;
            s1 += p2 + p3;
        }
        s0 += __shfl_xor_sync(0xFFFFFFFFu, s0, 1);
        s0 += __shfl_xor_sync(0xFFFFFFFFu, s0, 2);
        s1 += __shfl_xor_sync(0xFFFFFFFFu, s1, 1);
        s1 += __shfl_xor_sync(0xFFFFFFFFu, s1, 2);
        if (kc4 == 0) { rs[r0][warp & 1] = s0; rs[r0 + 8][warp & 1] = s1; }
    }
    __syncthreads();
    {
        float t = rs[tid][0] + rs[tid][1];
        g_rowsum_part[jb][(size_t)b * LQ + i0 + tid] = t;
    }
}

// ===== Kernel 2: inv per row for a batch pair (fixed order) =====
__global__ void k_rowsum(int b2)
{
    const int row = b2 * LQ + blockIdx.x * 256 + threadIdx.x;
    float s = 0.0f;
    #pragma unroll
    for (int jb = 0; jb < 16; jb++) s += g_rowsum_part[jb][row];
    g_inv[row] = 1.0f / s;
}

// ===== Kernel 3: normalize attn in place + partial out = p^T @ (inv*v) =====
// R14-proven internals: 8 warps, 64x32 warp tiles. Pair-local: grid (16, 2, 8).
__global__ __launch_bounds__(256, 2) void k_av_norm(
    const float* __restrict__ v, float* __restrict__ attn, int b2)
{
    const int jb = blockIdx.x;
    const int bl = blockIdx.y;           // local batch 0/1
    const int b  = b2 + bl;
    const int ks = blockIdx.z;           // 0..7
    const int j0 = jb * 128;
    const int ibase = ks * (LQ / KSPLIT);   // 256-wide K slice

    __shared__ float As[2][16][136];
    __shared__ float Bs[2][16][136];
    __shared__ float Is[2][16];

    const int tid  = threadIdx.x;
    const int lane = tid & 31;
    const int warp = tid >> 5;
    const int wm = (warp >> 2) * 64;
    const int wn = (warp & 3) * 32;
    const int g  = lane >> 2;

    float* ab = attn + (size_t)b * LQ * LQ + j0;
    const float* wb = v + (size_t)b * LQ * DIM;
    const float* iv = g_inv + (size_t)b * LQ;

    const int kr  = warp;
    const int lc4 = lane * 4;

    float acc[4][4][4];
    #pragma unroll
    for (int mt = 0; mt < 4; mt++)
        #pragma unroll
        for (int nt = 0; nt < 4; nt++)
            #pragma unroll
            for (int e = 0; e < 4; e++) acc[mt][nt][e] = 0.0f;

    {
        const int i0 = ibase;
        cp16(&As[0][kr][lc4],     ab + (size_t)(i0 + kr) * LQ + lc4);
        cp16(&As[0][kr + 8][lc4], ab + (size_t)(i0 + kr + 8) * LQ + lc4);
        cp16(&Bs[0][kr][lc4],     wb + (size_t)(i0 + kr) * DIM + lc4);
        cp16(&Bs[0][kr + 8][lc4], wb + (size_t)(i0 + kr + 8) * DIM + lc4);
        if (tid < 16) cp4(&Is[0][tid], iv + i0 + tid);
        CPC;
    }

    const int NIT = (LQ / KSPLIT) / 16;   // 16
    #pragma unroll 2
    for (int kt = 0; kt < NIT; kt++) {
        const int st = kt & 1;
        if (kt < NIT - 1) {
            const int i0n = ibase + (kt + 1) * 16;
            const int sn = st ^ 1;
            cp16(&As[sn][kr][lc4],     ab + (size_t)(i0n + kr) * LQ + lc4);
            cp16(&As[sn][kr + 8][lc4], ab + (size_t)(i0n + kr + 8) * LQ + lc4);
            cp16(&Bs[sn][kr][lc4],     wb + (size_t)(i0n + kr) * DIM + lc4);
            cp16(&Bs[sn][kr + 8][lc4], wb + (size_t)(i0n + kr + 8) * DIM + lc4);
            if (tid < 16) cp4(&Is[sn][tid], iv + i0n + tid);
            CPC; CPW1;
        } else {
            CPW0;
        }
        __syncthreads();

        // write back normalized attn (each element exactly once across grid)
        {
            const int i0 = ibase + kt * 16;
            const float iv0 = Is[st][kr], iv1 = Is[st][kr + 8];
            float4 a0 = *(const float4*)&As[st][kr][lc4];
            float4 a1 = *(const float4*)&As[st][kr + 8][lc4];
            a0.x *= iv0; a0.y *= iv0; a0.z *= iv0; a0.w *= iv0;
            a1.x *= iv1; a1.y *= iv1; a1.z *= iv1; a1.w *= iv1;
            *(float4*)(ab + (size_t)(i0 + kr) * LQ + lc4)     = a0;
            *(float4*)(ab + (size_t)(i0 + kr + 8) * LQ + lc4) = a1;
        }

        #pragma unroll
        for (int kk = 0; kk < 16; kk += 8) {
            const int kc = kk + (lane & 3);
            const float ic0 = Is[st][kc], ic4 = Is[st][kc + 4];
            float af[4][4], bf[4][2];
            #pragma unroll
            for (int mt = 0; mt < 4; mt++) {
                const int m = wm + mt * 16 + g;
                af[mt][0] = As[st][kc][m];
                af[mt][1] = As[st][kc][m + 8];
                af[mt][2] = As[st][kc + 4][m];
                af[mt][3] = As[st][kc + 4][m + 8];
            }
            #pragma unroll
            for (int nt = 0; nt < 4; nt++) {
                const int n = wn + nt * 8 + g;
                bf[nt][0] = tf32r(Bs[st][kc][n] * ic0);
                bf[nt][1] = tf32r(Bs[st][kc + 4][n] * ic4);
            }
            #pragma unroll
            for (int mt = 0; mt < 4; mt++)
                #pragma unroll
                for (int nt = 0; nt < 4; nt++)
                    mma8(acc[mt][nt], af[mt], bf[nt]);
        }
        __syncthreads();
    }

    // epilogue -> pair-local split-K partial buffer
    float* op = g_pout[ks] + ((size_t)bl * LQ + j0) * DIM;
    #pragma unroll
    for (int mt = 0; mt < 4; mt++) {
        const int r0 = wm + mt * 16 + g;
        #pragma unroll
        for (int nt = 0; nt < 4; nt++) {
            const int c0 = wn + nt * 8 + (lane & 3) * 2;
            *(float2*)(op + (size_t)r0 * DIM + c0)       = make_float2(acc[mt][nt][0], acc[mt][nt][1]);
            *(float2*)(op + (size_t)(r0 + 8) * DIM + c0) = make_float2(acc[mt][nt][2], acc[mt][nt][3]);
        }
    }
}

// ===== Kernel 4: out(pair) = sum over 8 split-K partials (fixed order) =====
__global__ void k_out_reduce(float* __restrict__ out, int b2)
{
    const size_t i = ((size_t)blockIdx.x * 256 + threadIdx.x) * 4;
    float4 a = *(const float4*)&g_pout[0][i];
    #pragma unroll
    for (int ks = 1; ks < KSPLIT; ks++) {
        float4 p = *(const float4*)&g_pout[ks][i];
        a.x += p.x; a.y += p.y; a.z += p.z; a.w += p.w;
    }
    *(float4*)(out + (size_t)b2 * LQ * DIM + i) = a;
}

// ===== launch: 4 batch-pairs, each L2-blocked =====
extern "C" void kernel_launch(void* const* d_in, const int* in_sizes, int n_in,
                              void* d_out, int out_size)
{
    const float* q = (const float*)d_in[0];
    // d_in[1] = k : unused by the reference computation
    const float* v = (const float*)d_in[2];

    float* out  = (float*)d_out;                 // [8, 2048, 128]
    float* attn = out + (size_t)NB * LQ * DIM;   // [8, 2048, 2048]

    for (int b2 = 0; b2 < NB; b2 += 2) {
        k_scores_exp<<<dim3(16, 16, 2), 128>>>(q, v, attn, b2);
        k_rowsum<<<(2 * LQ) / 256, 256>>>(b2);
        k_av_norm<<<dim3(16, 2, KSPLIT), 256>>>(v, attn, b2);
        k_out_reduce<<<PAIR_ELE / 1024, 256>>>(out, b2);
    }
}

// round 17
// speedup vs baseline: 1.2776x; 1.2776x over previous
#include <cuda_runtime.h>
#include <cstdint>

#define LQ 2048
#define DIM 128
#define NB 8
#define KSPLIT 2
#define ROWS (NB*LQ)
#define NELE ((size_t)ROWS * DIM)

// deterministic scratch (no allocations allowed)
__device__ float g_rowsum_part[16][ROWS];        // 1 MB
__device__ float g_inv[ROWS];                    // 64 KB

// ---------- helpers ----------
static __device__ __forceinline__ float tf32r(float x) {
    uint32_t u;
    asm("cvt.rna.tf32.f32 %0, %1;" : "=r"(u) : "f"(x));
    return __uint_as_float(u);
}
static __device__ __forceinline__ float ex2f(float x) {
    float r;
    asm("ex2.approx.f32 %0, %1;" : "=f"(r) : "f"(x));
    return r;
}

static __device__ __forceinline__ void mma8(float c[4], const float a[4], const float b[2]) {
    asm volatile(
        "mma.sync.aligned.m16n8k8.row.col.f32.tf32.tf32.f32 "
        "{%0,%1,%2,%3}, {%4,%5,%6,%7}, {%8,%9}, {%0,%1,%2,%3};\n"
        : "+f"(c[0]), "+f"(c[1]), "+f"(c[2]), "+f"(c[3])
        : "r"(__float_as_uint(a[0])), "r"(__float_as_uint(a[1])),
          "r"(__float_as_uint(a[2])), "r"(__float_as_uint(a[3])),
          "r"(__float_as_uint(b[0])), "r"(__float_as_uint(b[1])));
}

static __device__ __forceinline__ void cp16(void* dst, const void* src) {
    unsigned sd = (unsigned)__cvta_generic_to_shared(dst);
    asm volatile("cp.async.ca.shared.global [%0], [%1], 16;" :: "r"(sd), "l"(src));
}
static __device__ __forceinline__ void cp4(void* dst, const void* src) {
    unsigned sd = (unsigned)__cvta_generic_to_shared(dst);
    asm volatile("cp.async.ca.shared.global [%0], [%1], 4;" :: "r"(sd), "l"(src));
}
#define CPC  asm volatile("cp.async.commit_group;")
#define CPW1 asm volatile("cp.async.wait_group 1;")
#define CPW0 asm volatile("cp.async.wait_group 0;")

// ===== Kernel 1: p = tf32(exp((tf32(q) @ tf32(v)^T) * sc)) + rowsum partials =====
// 4 warps, 64x64 warp tiles (R8/R14-proven). Also zero-inits a disjoint 1KB out slice.
__global__ __launch_bounds__(128, 2) void k_scores_exp(
    const float* __restrict__ q, const float* __restrict__ v,
    float* __restrict__ attn, float* __restrict__ out)
{
    __shared__ float Qs[2][128][20];
    __shared__ float Vs[2][128][20];
    __shared__ float rs[128][2];

    const int b  = blockIdx.z;
    const int jb = blockIdx.x;
    const int i0 = blockIdx.y * 128;
    const int j0 = jb * 128;

    const int tid  = threadIdx.x;
    const int lane = tid & 31;
    const int warp = tid >> 5;          // 0..3
    const int wm = (warp >> 1) * 64;
    const int wn = (warp & 1) * 64;
    const int g   = lane >> 2;
    const int kc4 = lane & 3;

    // zero-init out slice: 2048 CTAs x 1024 floats = 2M floats
    {
        const size_t base = ((size_t)(blockIdx.z * 256 + blockIdx.y * 16 + blockIdx.x)) * 1024;
        *(float4*)(out + base + tid * 4)       = make_float4(0.f, 0.f, 0.f, 0.f);
        *(float4*)(out + base + 512 + tid * 4) = make_float4(0.f, 0.f, 0.f, 0.f);
    }

    const float* qb = q + ((size_t)b * LQ + i0) * DIM;
    const float* vb = v + ((size_t)b * LQ + j0) * DIM;

    const int lr  = tid >> 2;           // 0..31
    const int lcc = (tid & 3) * 4;      // 0,4,8,12

    float acc[4][8][4];
    #pragma unroll
    for (int mt = 0; mt < 4; mt++)
        #pragma unroll
        for (int nt = 0; nt < 8; nt++)
            #pragma unroll
            for (int e = 0; e < 4; e++) acc[mt][nt][e] = 0.0f;

    #pragma unroll
    for (int h = 0; h < 4; h++) {
        cp16(&Qs[0][lr + h * 32][lcc], qb + (size_t)(lr + h * 32) * DIM + lcc);
        cp16(&Vs[0][lr + h * 32][lcc], vb + (size_t)(lr + h * 32) * DIM + lcc);
    }
    CPC;

    #pragma unroll
    for (int kt = 0; kt < 8; kt++) {
        const int st = kt & 1;
        if (kt < 7) {
            const int k0 = (kt + 1) * 16;
            const int sn = st ^ 1;
            #pragma unroll
            for (int h = 0; h < 4; h++) {
                cp16(&Qs[sn][lr + h * 32][lcc], qb + (size_t)(lr + h * 32) * DIM + k0 + lcc);
                cp16(&Vs[sn][lr + h * 32][lcc], vb + (size_t)(lr + h * 32) * DIM + k0 + lcc);
            }
            CPC; CPW1;
        } else {
            CPW0;
        }
        __syncthreads();

        #pragma unroll
        for (int kk = 0; kk < 16; kk += 8) {
            const int kc = kk + kc4;
            float af[4][4], bf[8][2];
            #pragma unroll
            for (int mt = 0; mt < 4; mt++) {
                const int r = wm + mt * 16 + g;
                af[mt][0] = tf32r(Qs[st][r][kc]);
                af[mt][1] = tf32r(Qs[st][r + 8][kc]);
                af[mt][2] = tf32r(Qs[st][r][kc + 4]);
                af[mt][3] = tf32r(Qs[st][r + 8][kc + 4]);
            }
            #pragma unroll
            for (int nt = 0; nt < 8; nt++) {
                const int n = wn + nt * 8 + g;
                bf[nt][0] = tf32r(Vs[st][n][kc]);
                bf[nt][1] = tf32r(Vs[st][n][kc + 4]);
            }
            #pragma unroll
            for (int mt = 0; mt < 4; mt++)
                #pragma unroll
                for (int nt = 0; nt < 8; nt++)
                    mma8(acc[mt][nt], af[mt], bf[nt]);
        }
        __syncthreads();
    }

    // epilogue: p = tf32(ex2(acc * log2e/sqrt(128))), store, rowsum partials
    const float sc2 = 0.12752744244355965f;   // log2(e)/sqrt(128)
    float* op = attn + ((size_t)b * LQ + i0) * LQ + j0;
    #pragma unroll
    for (int mt = 0; mt < 4; mt++) {
        const int r0 = wm + mt * 16 + g;
        float s0 = 0.0f, s1 = 0.0f;
        #pragma unroll
        for (int nt = 0; nt < 8; nt++) {
            const int c0 = wn + nt * 8 + kc4 * 2;
            float p0 = tf32r(ex2f(acc[mt][nt][0] * sc2));
            float p1 = tf32r(ex2f(acc[mt][nt][1] * sc2));
            float p2 = tf32r(ex2f(acc[mt][nt][2] * sc2));
            float p3 = tf32r(ex2f(acc[mt][nt][3] * sc2));
            *(float2*)(op + (size_t)r0 * LQ + c0)       = make_float2(p0, p1);
            *(float2*)(op + (size_t)(r0 + 8) * LQ + c0) = make_float2(p2, p3);
            s0 += p0 + p1;
            s1 += p2 + p3;
        }
        s0 += __shfl_xor_sync(0xFFFFFFFFu, s0, 1);
        s0 += __shfl_xor_sync(0xFFFFFFFFu, s0, 2);
        s1 += __shfl_xor_sync(0xFFFFFFFFu, s1, 1);
        s1 += __shfl_xor_sync(0xFFFFFFFFu, s1, 2);
        if (kc4 == 0) { rs[r0][warp & 1] = s0; rs[r0 + 8][warp & 1] = s1; }
    }
    __syncthreads();
    {
        float t = rs[tid][0] + rs[tid][1];
        g_rowsum_part[jb][(size_t)b * LQ + i0 + tid] = t;
    }
}

// ===== Kernel 2: inv per row (fixed order) =====
__global__ void k_rowsum()
{
    const int row = blockIdx.x * 256 + threadIdx.x;
    float s = 0.0f;
    #pragma unroll
    for (int jb = 0; jb < 16; jb++) s += g_rowsum_part[jb][row];
    g_inv[row] = 1.0f / s;
}

// ===== Kernel 3: normalize attn in place + out += p^T @ (inv*v)  (atomic split-K) =====
// R14-proven internals: 8 warps, 64x32 warp tiles, KSPLIT=2.
__global__ __launch_bounds__(256, 2) void k_av_norm(
    const float* __restrict__ v, float* __restrict__ attn, float* __restrict__ out)
{
    const int jb = blockIdx.x;
    const int b  = blockIdx.y;
    const int ks = blockIdx.z;
    const int j0 = jb * 128;
    const int ibase = ks * (LQ / KSPLIT);

    __shared__ float As[2][16][136];
    __shared__ float Bs[2][16][136];
    __shared__ float Is[2][16];

    const int tid  = threadIdx.x;
    const int lane = tid & 31;
    const int warp = tid >> 5;
    const int wm = (warp >> 2) * 64;
    const int wn = (warp & 3) * 32;
    const int g  = lane >> 2;

    float* ab = attn + (size_t)b * LQ * LQ + j0;
    const float* wb = v + (size_t)b * LQ * DIM;
    const float* iv = g_inv + (size_t)b * LQ;

    const int kr  = warp;
    const int lc4 = lane * 4;

    float acc[4][4][4];
    #pragma unroll
    for (int mt = 0; mt < 4; mt++)
        #pragma unroll
        for (int nt = 0; nt < 4; nt++)
            #pragma unroll
            for (int e = 0; e < 4; e++) acc[mt][nt][e] = 0.0f;

    {
        const int i0 = ibase;
        cp16(&As[0][kr][lc4],     ab + (size_t)(i0 + kr) * LQ + lc4);
        cp16(&As[0][kr + 8][lc4], ab + (size_t)(i0 + kr + 8) * LQ + lc4);
        cp16(&Bs[0][kr][lc4],     wb + (size_t)(i0 + kr) * DIM + lc4);
        cp16(&Bs[0][kr + 8][lc4], wb + (size_t)(i0 + kr + 8) * DIM + lc4);
        if (tid < 16) cp4(&Is[0][tid], iv + i0 + tid);
        CPC;
    }

    const int NIT = (LQ / KSPLIT) / 16;   // 64
    #pragma unroll 2
    for (int kt = 0; kt < NIT; kt++) {
        const int st = kt & 1;
        if (kt < NIT - 1) {
            const int i0n = ibase + (kt + 1) * 16;
            const int sn = st ^ 1;
            cp16(&As[sn][kr][lc4],     ab + (size_t)(i0n + kr) * LQ + lc4);
            cp16(&As[sn][kr + 8][lc4], ab + (size_t)(i0n + kr + 8) * LQ + lc4);
            cp16(&Bs[sn][kr][lc4],     wb + (size_t)(i0n + kr) * DIM + lc4);
            cp16(&Bs[sn][kr + 8][lc4], wb + (size_t)(i0n + kr + 8) * DIM + lc4);
            if (tid < 16) cp4(&Is[sn][tid], iv + i0n + tid);
            CPC; CPW1;
        } else {
            CPW0;
        }
        __syncthreads();

        // write back normalized attn (each element exactly once across grid)
        {
            const int i0 = ibase + kt * 16;
            const float iv0 = Is[st][kr], iv1 = Is[st][kr + 8];
            float4 a0 = *(const float4*)&As[st][kr][lc4];
            float4 a1 = *(const float4*)&As[st][kr + 8][lc4];
            a0.x *= iv0; a0.y *= iv0; a0.z *= iv0; a0.w *= iv0;
            a1.x *= iv1; a1.y *= iv1; a1.z *= iv1; a1.w *= iv1;
            *(float4*)(ab + (size_t)(i0 + kr) * LQ + lc4)     = a0;
            *(float4*)(ab + (size_t)(i0 + kr + 8) * LQ + lc4) = a1;
        }

        #pragma unroll
        for (int kk = 0; kk < 16; kk += 8) {
            const int kc = kk + (lane & 3);
            const float ic0 = Is[st][kc], ic4 = Is[st][kc + 4];
            float af[4][4], bf[4][2];
            #pragma unroll
            for (int mt = 0; mt < 4; mt++) {
                const int m = wm + mt * 16 + g;
                af[mt][0] = As[st][kc][m];
                af[mt][1] = As[st][kc][m + 8];
                af[mt][2] = As[st][kc + 4][m];
                af[mt][3] = As[st][kc + 4][m + 8];
            }
            #pragma unroll
            for (int nt = 0; nt < 4; nt++) {
                const int n = wn + nt * 8 + g;
                bf[nt][0] = tf32r(Bs[st][kc][n] * ic0);
                bf[nt][1] = tf32r(Bs[st][kc + 4][n] * ic4);
            }
            #pragma unroll
            for (int mt = 0; mt < 4; mt++)
                #pragma unroll
                for (int nt = 0; nt < 4; nt++)
                    mma8(acc[mt][nt], af[mt], bf[nt]);
        }
        __syncthreads();
    }

    // epilogue: atomic accumulate into out (2 commutative adds per element -> deterministic)
    float* op = out + ((size_t)b * LQ + j0) * DIM;
    #pragma unroll
    for (int mt = 0; mt < 4; mt++) {
        const int r0 = wm + mt * 16 + g;
        #pragma unroll
        for (int nt = 0; nt < 4; nt++) {
            const int c0 = wn + nt * 8 + (lane & 3) * 2;
            atomicAdd(op + (size_t)r0 * DIM + c0,           acc[mt][nt][0]);
            atomicAdd(op + (size_t)r0 * DIM + c0 + 1,       acc[mt][nt][1]);
            atomicAdd(op + (size_t)(r0 + 8) * DIM + c0,     acc[mt][nt][2]);
            atomicAdd(op + (size_t)(r0 + 8) * DIM + c0 + 1, acc[mt][nt][3]);
        }
    }
}

// ===== launch =====
extern "C" void kernel_launch(void* const* d_in, const int* in_sizes, int n_in,
                              void* d_out, int out_size)
{
    const float* q = (const float*)d_in[0];
    // d_in[1] = k : unused by the reference computation
    const float* v = (const float*)d_in[2];

    float* out  = (float*)d_out;                 // [8, 2048, 128]
    float* attn = out + (size_t)NB * LQ * DIM;   // [8, 2048, 2048]

    k_scores_exp<<<dim3(16, 16, NB), 128>>>(q, v, attn, out);
    k_rowsum<<<ROWS / 256, 256>>>();
    k_av_norm<<<dim3(16, NB, KSPLIT), 256>>>(v, attn, out);
}